// round 2
// baseline (speedup 1.0000x reference)
#include <cuda_runtime.h>

namespace {
constexpr int Bn = 256, Tn = 64, Mn = 256, Hn = 256, K2H = 512, G4H = 1024;
}

// ---------------- device scratch (no allocations allowed) ----------------
__device__ float g_enc[Bn * Tn * Mn];   // enc (b,t,m)
__device__ float g_y1 [Bn * Tn * Mn];   // enc @ U_d^T
__device__ float g_S  [Bn * K2H];       // [d | sp] per batch row
__device__ float g_x1 [Bn * Mn];
__device__ float g_G1 [Bn * G4H];
__device__ float g_c  [Bn * Mn];
__device__ float g_gbias[G4H];          // b_ih + b_hh
__device__ float g_wv [513];            // folded W_y/v_y projection + const

__device__ __forceinline__ float fast_tanh(float x) {
    float e = __expf(2.f * x);
    return 1.f - __fdividef(2.f, e + 1.f);
}
__device__ __forceinline__ float sigm(float x) {
    return __fdividef(1.f, 1.f + __expf(-x));
}

// ---------------- prep: transpose enc, zero state, fold gate bias --------
__global__ void k_pre(const float* __restrict__ enc_in,
                      const float* __restrict__ b_ih,
                      const float* __restrict__ b_hh) {
    int idx = blockIdx.x * blockDim.x + threadIdx.x;
    int stride = gridDim.x * blockDim.x;
    for (int i = idx; i < Bn * Tn * Mn; i += stride) {
        int m = i & (Mn - 1);
        int t = (i >> 8) & (Tn - 1);
        int b = i >> 14;
        g_enc[i] = enc_in[(size_t)t * Bn * Mn + (size_t)b * Mn + m];
    }
    for (int i = idx; i < Bn * K2H; i += stride) g_S[i] = 0.f;
    for (int i = idx; i < G4H; i += stride) g_gbias[i] = b_ih[i] + b_hh[i];
}

// ---------------- fold final projection ----------------------------------
__global__ void k_wv(const float* __restrict__ W_y, const float* __restrict__ v_y,
                     const float* __restrict__ b_Wy, const float* __restrict__ b_vy) {
    int k = threadIdx.x;  // 512 threads
    float s = 0.f;
    for (int j = 0; j < Hn; j++) s += v_y[j] * W_y[(size_t)j * K2H + k];
    g_wv[k] = s;
    if (k == 0) {
        float s0 = 0.f;
        for (int j = 0; j < Hn; j++) s0 += v_y[j] * b_Wy[j];
        g_wv[512] = s0 + b_vy[0];
    }
}

// ---------------- tiled fp32 GEMM: C[m,n] = sum_k A[m,k]*W[n,k] + bias[n] --
// 128 threads, 64x32 tile, BK=16, 4x4 register block per thread.
__device__ __forceinline__ void gemm_tile_body(
    const float* __restrict__ A, int lda,
    const float* __restrict__ W, int ldw,
    float* __restrict__ C, int ldc,
    const float* __restrict__ bias,
    int m0, int n0, int K) {

    __shared__ __align__(16) float As[16 * 64];
    __shared__ __align__(16) float Ws[16 * 32];

    const int tid = threadIdx.x;
    const int tm = tid >> 3;             // 0..15
    const int tn = tid & 7;              // 0..7
    const int ar = tid >> 1;             // 0..63
    const int ac = (tid & 1) << 3;       // {0,8}
    const int wr = tid >> 2;             // 0..31
    const int wc = (tid & 3) << 2;       // {0,4,8,12}

    float acc[4][4];
#pragma unroll
    for (int i = 0; i < 4; i++)
#pragma unroll
        for (int j = 0; j < 4; j++) acc[i][j] = 0.f;

    for (int k0 = 0; k0 < K; k0 += 16) {
        float4 a0 = *(const float4*)(A + (size_t)(m0 + ar) * lda + k0 + ac);
        float4 a1 = *(const float4*)(A + (size_t)(m0 + ar) * lda + k0 + ac + 4);
        float4 w0 = *(const float4*)(W + (size_t)(n0 + wr) * ldw + k0 + wc);
        As[(ac + 0) * 64 + ar] = a0.x; As[(ac + 1) * 64 + ar] = a0.y;
        As[(ac + 2) * 64 + ar] = a0.z; As[(ac + 3) * 64 + ar] = a0.w;
        As[(ac + 4) * 64 + ar] = a1.x; As[(ac + 5) * 64 + ar] = a1.y;
        As[(ac + 6) * 64 + ar] = a1.z; As[(ac + 7) * 64 + ar] = a1.w;
        Ws[(wc + 0) * 32 + wr] = w0.x; Ws[(wc + 1) * 32 + wr] = w0.y;
        Ws[(wc + 2) * 32 + wr] = w0.z; Ws[(wc + 3) * 32 + wr] = w0.w;
        __syncthreads();
#pragma unroll
        for (int k = 0; k < 16; k++) {
            float4 av = *(const float4*)(As + k * 64 + 4 * tm);
            float4 wv = *(const float4*)(Ws + k * 32 + 4 * tn);
            acc[0][0] += av.x * wv.x; acc[0][1] += av.x * wv.y;
            acc[0][2] += av.x * wv.z; acc[0][3] += av.x * wv.w;
            acc[1][0] += av.y * wv.x; acc[1][1] += av.y * wv.y;
            acc[1][2] += av.y * wv.z; acc[1][3] += av.y * wv.w;
            acc[2][0] += av.z * wv.x; acc[2][1] += av.z * wv.y;
            acc[2][2] += av.z * wv.z; acc[2][3] += av.z * wv.w;
            acc[3][0] += av.w * wv.x; acc[3][1] += av.w * wv.y;
            acc[3][2] += av.w * wv.z; acc[3][3] += av.w * wv.w;
        }
        __syncthreads();
    }
#pragma unroll
    for (int i = 0; i < 4; i++) {
        int m = m0 + 4 * tm + i;
        int n = n0 + 4 * tn;
        float4 bv;
        if (bias) bv = *(const float4*)(bias + n);
        else { bv.x = bv.y = bv.z = bv.w = 0.f; }
        float4 cv;
        cv.x = acc[i][0] + bv.x; cv.y = acc[i][1] + bv.y;
        cv.z = acc[i][2] + bv.z; cv.w = acc[i][3] + bv.w;
        *(float4*)(C + (size_t)m * ldc + n) = cv;
    }
}

__global__ void k_y1(const float* __restrict__ U_d) {
    gemm_tile_body(g_enc, Mn, U_d, Mn, g_y1, Mn, nullptr,
                   blockIdx.y * 64, blockIdx.x * 32, Mn);
}

// blocks 0..31: x1 = S @ W_d^T + b_Wd   (256x256, K=512)
// blocks 32..159: G1 = d @ W_hh^T + gbias (256x1024, K=256)
__global__ void k_stepgemm(const float* __restrict__ W_d,
                           const float* __restrict__ b_Wd,
                           const float* __restrict__ W_hh) {
    int id = blockIdx.x;
    if (id < 32) {
        gemm_tile_body(g_S, K2H, W_d, K2H, g_x1, Mn, b_Wd,
                       (id >> 3) * 64, (id & 7) * 32, K2H);
    } else {
        int j = id - 32;
        gemm_tile_body(g_S, K2H, W_hh, Hn, g_G1, G4H, g_gbias,
                       (j >> 5) * 64, (j & 31) * 32, Hn);
    }
}

// ---------------- per-batch attention + LSTM cell update ------------------
__global__ void k_attn(const float* __restrict__ y_in, const float* __restrict__ v_d,
                       const float* __restrict__ w_til, const float* __restrict__ b_wt,
                       const float* __restrict__ W_ih, int t_step) {
    int b = blockIdx.x, tid = threadIdx.x;
    int warp = tid >> 5, lane = tid & 31;
    __shared__ float sx[Mn], sv[Mn], sl[Tn], sred[8];
    __shared__ float s_ytil;

    sx[tid] = g_x1[b * Mn + tid];
    sv[tid] = v_d[tid];
    __syncthreads();

    const float* y1b = g_y1 + (size_t)b * Tn * Mn;
    // l[t] = sum_m tanh(x1[m] + y1[t,m]) * v_d[m]; warp handles 8 t values
#pragma unroll
    for (int i = 0; i < 8; i++) {
        int t = warp * 8 + i;
        const float* row = y1b + t * Mn;
        float acc = 0.f;
#pragma unroll
        for (int j = 0; j < 8; j++) {
            int m = lane + 32 * j;
            acc += fast_tanh(sx[m] + row[m]) * sv[m];
        }
#pragma unroll
        for (int o = 16; o > 0; o >>= 1) acc += __shfl_xor_sync(0xffffffffu, acc, o);
        if (lane == 0) sl[t] = acc;
    }
    __syncthreads();

    // softmax over 64 (warp 0, 2 values per lane)
    if (warp == 0) {
        float v0 = sl[lane], v1 = sl[lane + 32];
        float mx = fmaxf(v0, v1);
#pragma unroll
        for (int o = 16; o > 0; o >>= 1) mx = fmaxf(mx, __shfl_xor_sync(0xffffffffu, mx, o));
        float e0 = __expf(v0 - mx), e1 = __expf(v1 - mx);
        float s = e0 + e1;
#pragma unroll
        for (int o = 16; o > 0; o >>= 1) s += __shfl_xor_sync(0xffffffffu, s, o);
        float inv = __fdividef(1.f, s);
        sl[lane] = e0 * inv; sl[lane + 32] = e1 * inv;
    }
    __syncthreads();

    // context c[m] = sum_t beta[t] * enc[b,t,m]
    const float* encb = g_enc + (size_t)b * Tn * Mn;
    float c = 0.f;
#pragma unroll 8
    for (int t = 0; t < Tn; t++) c += sl[t] * encb[t * Mn + tid];
    g_c[b * Mn + tid] = c;

    // y_til = c . w_tilda[0:M] + w_tilda[M]*y_t + b_wt
    float part = c * w_til[tid];
#pragma unroll
    for (int o = 16; o > 0; o >>= 1) part += __shfl_xor_sync(0xffffffffu, part, o);
    if (lane == 0) sred[warp] = part;
    __syncthreads();
    if (tid == 0) {
        float s = 0.f;
#pragma unroll
        for (int w = 0; w < 8; w++) s += sred[w];
        s_ytil = s + w_til[Mn] * y_in[b * Tn + t_step] + b_wt[0];
    }
    __syncthreads();
    float yt = s_ytil;

    // LSTM cell: gates = yt*W_ih + G1 (G1 already has d@W_hh^T + both biases)
    const float* G1b = g_G1 + b * G4H;
    float ig = yt * W_ih[tid]          + G1b[tid];
    float fg = yt * W_ih[Hn + tid]     + G1b[Hn + tid];
    float gg = yt * W_ih[2 * Hn + tid] + G1b[2 * Hn + tid];
    float og = yt * W_ih[3 * Hn + tid] + G1b[3 * Hn + tid];
    float sp = g_S[b * K2H + Hn + tid];
    float spn = sigm(fg) * sp + sigm(ig) * fast_tanh(gg);
    float dn  = sigm(og) * fast_tanh(spn);
    g_S[b * K2H + tid]      = dn;
    g_S[b * K2H + Hn + tid] = spn;
}

// ---------------- folded output: out[b] = [d|c] . wv + const --------------
__global__ void k_out(float* __restrict__ out) {
    int b = blockIdx.x, tid = threadIdx.x;
    int warp = tid >> 5, lane = tid & 31;
    __shared__ float sred[8];
    float p = g_S[b * K2H + tid] * g_wv[tid] + g_c[b * Mn + tid] * g_wv[Hn + tid];
#pragma unroll
    for (int o = 16; o > 0; o >>= 1) p += __shfl_xor_sync(0xffffffffu, p, o);
    if (lane == 0) sred[warp] = p;
    __syncthreads();
    if (tid == 0) {
        float s = 0.f;
#pragma unroll
        for (int w = 0; w < 8; w++) s += sred[w];
        out[b] = s + g_wv[512];
    }
}

extern "C" void kernel_launch(void* const* d_in, const int* in_sizes, int n_in,
                              void* d_out, int out_size) {
    const float* enc  = (const float*)d_in[0];
    const float* y    = (const float*)d_in[1];
    const float* W_d  = (const float*)d_in[2];
    const float* b_Wd = (const float*)d_in[3];
    const float* U_d  = (const float*)d_in[4];
    const float* v_d  = (const float*)d_in[5];
    const float* w_t  = (const float*)d_in[6];
    const float* b_wt = (const float*)d_in[7];
    const float* W_ih = (const float*)d_in[8];
    const float* W_hh = (const float*)d_in[9];
    const float* b_ih = (const float*)d_in[10];
    const float* b_hh = (const float*)d_in[11];
    const float* W_y  = (const float*)d_in[12];
    const float* b_Wy = (const float*)d_in[13];
    const float* v_y  = (const float*)d_in[14];
    const float* b_vy = (const float*)d_in[15];

    k_pre<<<2048, 256>>>(enc, b_ih, b_hh);
    k_wv<<<1, 512>>>(W_y, v_y, b_Wy, b_vy);
    k_y1<<<dim3(Mn / 32, (Bn * Tn) / 64), 128>>>(U_d);
    for (int t = 0; t < Tn; t++) {
        k_stepgemm<<<160, 128>>>(W_d, b_Wd, W_hh);
        k_attn<<<256, 256>>>(y, v_d, w_t, b_wt, W_ih, t);
    }
    k_out<<<256, 256>>>((float*)d_out);
}

// round 3
// speedup vs baseline: 1.2600x; 1.2600x over previous
#include <cuda_runtime.h>

namespace {
constexpr int Bn = 256, Tn = 64, Mn = 256, Hn = 256, K2H = 512, G4H = 1024;
}

// ---------------- device scratch (no allocations allowed) ----------------
__device__ float g_enc[Bn * Tn * Mn];   // enc (b,t,m)
__device__ float g_y1 [Bn * Tn * Mn];   // enc @ U_d^T
__device__ float g_S  [Bn * K2H];       // [d | sp] per batch row
__device__ float g_x1 [Bn * Mn];
__device__ float g_G1 [Bn * G4H];
__device__ float g_c  [Bn * Mn];
__device__ float g_gbias[G4H];          // b_ih + b_hh
__device__ float g_wv [513];            // folded W_y/v_y projection + const

__device__ __forceinline__ float tanh_mufu(float x) {      // attention only
    float y; asm("tanh.approx.f32 %0, %1;" : "=f"(y) : "f"(x)); return y;
}
__device__ __forceinline__ float tanh_acc(float x) {       // LSTM gates
    float e = __expf(2.f * x);
    return 1.f - __fdividef(2.f, e + 1.f);
}
__device__ __forceinline__ float sigm(float x) {
    return __fdividef(1.f, 1.f + __expf(-x));
}

// ---------------- prep: transpose enc, zero state, fold gate bias --------
__global__ void k_pre(const float* __restrict__ enc_in,
                      const float* __restrict__ b_ih,
                      const float* __restrict__ b_hh) {
    int idx = blockIdx.x * blockDim.x + threadIdx.x;
    int stride = gridDim.x * blockDim.x;
    for (int i = idx; i < Bn * Tn * Mn; i += stride) {
        int m = i & (Mn - 1);
        int t = (i >> 8) & (Tn - 1);
        int b = i >> 14;
        g_enc[i] = enc_in[(size_t)t * Bn * Mn + (size_t)b * Mn + m];
    }
    for (int i = idx; i < Bn * K2H; i += stride) g_S[i] = 0.f;
    for (int i = idx; i < G4H; i += stride) g_gbias[i] = b_ih[i] + b_hh[i];
}

// ---------------- fold final projection ----------------------------------
__global__ void k_wv(const float* __restrict__ W_y, const float* __restrict__ v_y,
                     const float* __restrict__ b_Wy, const float* __restrict__ b_vy) {
    int k = threadIdx.x;  // 512 threads
    float s = 0.f;
    for (int j = 0; j < Hn; j++) s += v_y[j] * W_y[(size_t)j * K2H + k];
    g_wv[k] = s;
    if (k == 0) {
        float s0 = 0.f;
        for (int j = 0; j < Hn; j++) s0 += v_y[j] * b_Wy[j];
        g_wv[512] = s0 + b_vy[0];
    }
}

// ---- GEMM partial: acc += A[m0+..][kb..ke) * W[n0+..][kb..ke)^T ----------
// 128 threads, 64x32 tile, BK=16, 4x4 regs per thread. As/Ws are per-group
// staging buffers (As: 16x64 k-major, Ws: 16x32 k-major).
__device__ __forceinline__ void gemm_partial(
    const float* __restrict__ A, int lda,
    const float* __restrict__ W, int ldw,
    int m0, int n0, int kb, int ke,
    float* __restrict__ As, float* __restrict__ Ws,
    float acc[4][4], int tid) {

    const int tm = tid >> 3;             // 0..15
    const int tn = tid & 7;              // 0..7
    const int ar = tid >> 1;             // 0..63
    const int ac = (tid & 1) << 3;       // {0,8}
    const int wr = tid >> 2;             // 0..31
    const int wc = (tid & 3) << 2;       // {0,4,8,12}

    for (int k0 = kb; k0 < ke; k0 += 16) {
        float4 a0 = *(const float4*)(A + (size_t)(m0 + ar) * lda + k0 + ac);
        float4 a1 = *(const float4*)(A + (size_t)(m0 + ar) * lda + k0 + ac + 4);
        float4 w0 = *(const float4*)(W + (size_t)(n0 + wr) * ldw + k0 + wc);
        As[(ac + 0) * 64 + ar] = a0.x; As[(ac + 1) * 64 + ar] = a0.y;
        As[(ac + 2) * 64 + ar] = a0.z; As[(ac + 3) * 64 + ar] = a0.w;
        As[(ac + 4) * 64 + ar] = a1.x; As[(ac + 5) * 64 + ar] = a1.y;
        As[(ac + 6) * 64 + ar] = a1.z; As[(ac + 7) * 64 + ar] = a1.w;
        Ws[(wc + 0) * 32 + wr] = w0.x; Ws[(wc + 1) * 32 + wr] = w0.y;
        Ws[(wc + 2) * 32 + wr] = w0.z; Ws[(wc + 3) * 32 + wr] = w0.w;
        __syncwarp();
        __syncthreads();
#pragma unroll
        for (int k = 0; k < 16; k++) {
            float4 av = *(const float4*)(As + k * 64 + 4 * tm);
            float4 wv = *(const float4*)(Ws + k * 32 + 4 * tn);
            acc[0][0] += av.x * wv.x; acc[0][1] += av.x * wv.y;
            acc[0][2] += av.x * wv.z; acc[0][3] += av.x * wv.w;
            acc[1][0] += av.y * wv.x; acc[1][1] += av.y * wv.y;
            acc[1][2] += av.y * wv.z; acc[1][3] += av.y * wv.w;
            acc[2][0] += av.z * wv.x; acc[2][1] += av.z * wv.y;
            acc[2][2] += av.z * wv.z; acc[2][3] += av.z * wv.w;
            acc[3][0] += av.w * wv.x; acc[3][1] += av.w * wv.y;
            acc[3][2] += av.w * wv.z; acc[3][3] += av.w * wv.w;
        }
        __syncthreads();
    }
}

// ---------------- per-step fused GEMM, 256 threads, intra-block split-K ---
// blocks 0..31  : x1 = S @ W_d^T  + b_Wd   (256x256,  K=512)
// blocks 32..159: G1 = d @ W_hh^T + gbias  (256x1024, K=256)
// Group g = tid>>7 computes K-half [g*K/2, (g+1)*K/2); groups reduce in SMEM.
__global__ void __launch_bounds__(256) k_stepgemm(
        const float* __restrict__ W_d, const float* __restrict__ b_Wd,
        const float* __restrict__ W_hh) {
    __shared__ __align__(16) float As[2][16 * 64];
    __shared__ __align__(16) float Ws[2][16 * 32];
    __shared__ __align__(16) float Red[64 * 32];

    const int g   = threadIdx.x >> 7;
    const int tid = threadIdx.x & 127;
    const int id  = blockIdx.x;

    const float* A; const float* W; float* C; const float* bias;
    int lda, ldw, ldc, m0, n0, K;
    if (id < 32) {
        A = g_S;  lda = K2H; W = W_d;  ldw = K2H; C = g_x1; ldc = Mn;
        bias = b_Wd;  m0 = (id >> 3) * 64; n0 = (id & 7) * 32; K = K2H;
    } else {
        int j = id - 32;
        A = g_S;  lda = K2H; W = W_hh; ldw = Hn;  C = g_G1; ldc = G4H;
        bias = g_gbias; m0 = (j >> 5) * 64; n0 = (j & 31) * 32; K = Hn;
    }

    float acc[4][4];
#pragma unroll
    for (int i = 0; i < 4; i++)
#pragma unroll
        for (int j = 0; j < 4; j++) acc[i][j] = 0.f;

    const int kh = K >> 1;
    gemm_partial(A, lda, W, ldw, m0, n0, g * kh, (g + 1) * kh,
                 As[g], Ws[g], acc, tid);

    const int tm = tid >> 3, tn = tid & 7;
    // group 0 deposits, group 1 adds + writes
    if (g == 0) {
#pragma unroll
        for (int i = 0; i < 4; i++)
            *(float4*)(Red + (4 * tm + i) * 32 + 4 * tn) = *(float4*)acc[i];
    }
    __syncthreads();
    if (g == 1) {
#pragma unroll
        for (int i = 0; i < 4; i++) {
            float4 r = *(const float4*)(Red + (4 * tm + i) * 32 + 4 * tn);
            int m = m0 + 4 * tm + i;
            int n = n0 + 4 * tn;
            float4 bv = *(const float4*)(bias + n);
            float4 cv;
            cv.x = acc[i][0] + r.x + bv.x; cv.y = acc[i][1] + r.y + bv.y;
            cv.z = acc[i][2] + r.z + bv.z; cv.w = acc[i][3] + r.w + bv.w;
            *(float4*)(C + (size_t)m * ldc + n) = cv;
        }
    }
}

// ---------------- one-time y1 GEMM (high grid occupancy already) ----------
__global__ void __launch_bounds__(128) k_y1(const float* __restrict__ U_d) {
    __shared__ __align__(16) float As[16 * 64];
    __shared__ __align__(16) float Ws[16 * 32];
    float acc[4][4];
#pragma unroll
    for (int i = 0; i < 4; i++)
#pragma unroll
        for (int j = 0; j < 4; j++) acc[i][j] = 0.f;
    int m0 = blockIdx.y * 64, n0 = blockIdx.x * 32;
    gemm_partial(g_enc, Mn, U_d, Mn, m0, n0, 0, Mn, As, Ws, acc, threadIdx.x);
    const int tm = threadIdx.x >> 3, tn = threadIdx.x & 7;
#pragma unroll
    for (int i = 0; i < 4; i++) {
        int m = m0 + 4 * tm + i;
        int n = n0 + 4 * tn;
        *(float4*)(g_y1 + (size_t)m * Mn + n) = *(float4*)acc[i];
    }
}

// ---------------- per-batch attention + LSTM cell update ------------------
__global__ void __launch_bounds__(256) k_attn(
        const float* __restrict__ y_in, const float* __restrict__ v_d,
        const float* __restrict__ w_til, const float* __restrict__ b_wt,
        const float* __restrict__ W_ih, int t_step) {
    int b = blockIdx.x, tid = threadIdx.x;
    int warp = tid >> 5, lane = tid & 31;
    __shared__ float sx[Mn], sv[Mn], sl[Tn], sred[8];
    __shared__ float s_ytil;

    sx[tid] = g_x1[b * Mn + tid];
    sv[tid] = v_d[tid];
    __syncthreads();

    const float* y1b = g_y1 + (size_t)b * Tn * Mn;
    // l[t] = sum_m tanh(x1[m] + y1[t,m]) * v_d[m]; warp handles 8 t values
#pragma unroll
    for (int i = 0; i < 8; i++) {
        int t = warp * 8 + i;
        const float* row = y1b + t * Mn;
        float acc = 0.f;
#pragma unroll
        for (int j = 0; j < 8; j++) {
            int m = lane + 32 * j;
            acc += tanh_mufu(sx[m] + row[m]) * sv[m];
        }
#pragma unroll
        for (int o = 16; o > 0; o >>= 1) acc += __shfl_xor_sync(0xffffffffu, acc, o);
        if (lane == 0) sl[t] = acc;
    }
    __syncthreads();

    // softmax over 64 (warp 0, 2 values per lane)
    if (warp == 0) {
        float v0 = sl[lane], v1 = sl[lane + 32];
        float mx = fmaxf(v0, v1);
#pragma unroll
        for (int o = 16; o > 0; o >>= 1) mx = fmaxf(mx, __shfl_xor_sync(0xffffffffu, mx, o));
        float e0 = __expf(v0 - mx), e1 = __expf(v1 - mx);
        float s = e0 + e1;
#pragma unroll
        for (int o = 16; o > 0; o >>= 1) s += __shfl_xor_sync(0xffffffffu, s, o);
        float inv = __fdividef(1.f, s);
        sl[lane] = e0 * inv; sl[lane + 32] = e1 * inv;
    }
    __syncthreads();

    // context c[m] = sum_t beta[t] * enc[b,t,m]
    const float* encb = g_enc + (size_t)b * Tn * Mn;
    float c = 0.f;
#pragma unroll 8
    for (int t = 0; t < Tn; t++) c += sl[t] * encb[t * Mn + tid];
    g_c[b * Mn + tid] = c;

    // y_til = c . w_tilda[0:M] + w_tilda[M]*y_t + b_wt
    float part = c * w_til[tid];
#pragma unroll
    for (int o = 16; o > 0; o >>= 1) part += __shfl_xor_sync(0xffffffffu, part, o);
    if (lane == 0) sred[warp] = part;
    __syncthreads();
    if (tid == 0) {
        float s = 0.f;
#pragma unroll
        for (int w = 0; w < 8; w++) s += sred[w];
        s_ytil = s + w_til[Mn] * y_in[b * Tn + t_step] + b_wt[0];
    }
    __syncthreads();
    float yt = s_ytil;

    // LSTM cell: gates = yt*W_ih + G1 (G1 already has d@W_hh^T + both biases)
    const float* G1b = g_G1 + b * G4H;
    float ig = yt * W_ih[tid]          + G1b[tid];
    float fg = yt * W_ih[Hn + tid]     + G1b[Hn + tid];
    float gg = yt * W_ih[2 * Hn + tid] + G1b[2 * Hn + tid];
    float og = yt * W_ih[3 * Hn + tid] + G1b[3 * Hn + tid];
    float sp = g_S[b * K2H + Hn + tid];
    float spn = sigm(fg) * sp + sigm(ig) * tanh_acc(gg);
    float dn  = sigm(og) * tanh_acc(spn);
    g_S[b * K2H + tid]      = dn;
    g_S[b * K2H + Hn + tid] = spn;
}

// ---------------- folded output: out[b] = [d|c] . wv + const --------------
__global__ void k_out(float* __restrict__ out) {
    int b = blockIdx.x, tid = threadIdx.x;
    int warp = tid >> 5, lane = tid & 31;
    __shared__ float sred[8];
    float p = g_S[b * K2H + tid] * g_wv[tid] + g_c[b * Mn + tid] * g_wv[Hn + tid];
#pragma unroll
    for (int o = 16; o > 0; o >>= 1) p += __shfl_xor_sync(0xffffffffu, p, o);
    if (lane == 0) sred[warp] = p;
    __syncthreads();
    if (tid == 0) {
        float s = 0.f;
#pragma unroll
        for (int w = 0; w < 8; w++) s += sred[w];
        out[b] = s + g_wv[512];
    }
}

extern "C" void kernel_launch(void* const* d_in, const int* in_sizes, int n_in,
                              void* d_out, int out_size) {
    const float* enc  = (const float*)d_in[0];
    const float* y    = (const float*)d_in[1];
    const float* W_d  = (const float*)d_in[2];
    const float* b_Wd = (const float*)d_in[3];
    const float* U_d  = (const float*)d_in[4];
    const float* v_d  = (const float*)d_in[5];
    const float* w_t  = (const float*)d_in[6];
    const float* b_wt = (const float*)d_in[7];
    const float* W_ih = (const float*)d_in[8];
    const float* W_hh = (const float*)d_in[9];
    const float* b_ih = (const float*)d_in[10];
    const float* b_hh = (const float*)d_in[11];
    const float* W_y  = (const float*)d_in[12];
    const float* b_Wy = (const float*)d_in[13];
    const float* v_y  = (const float*)d_in[14];
    const float* b_vy = (const float*)d_in[15];

    k_pre<<<2048, 256>>>(enc, b_ih, b_hh);
    k_wv<<<1, 512>>>(W_y, v_y, b_Wy, b_vy);
    k_y1<<<dim3(Mn / 32, (Bn * Tn) / 64), 128>>>(U_d);
    for (int t = 0; t < Tn; t++) {
        k_stepgemm<<<160, 256>>>(W_d, b_Wd, W_hh);
        k_attn<<<256, 256>>>(y, v_d, w_t, b_wt, W_ih, t);
    }
    k_out<<<256, 256>>>((float*)d_out);
}

// round 4
// speedup vs baseline: 1.8515x; 1.4695x over previous
#include <cuda_runtime.h>

namespace {
constexpr int Bn = 256, Tn = 64, Mn = 256, Hn = 256, K2H = 512, G4H = 1024;
}

// ---------------- device scratch (no allocations allowed) ----------------
__device__ float g_enc[Bn * Tn * Mn];    // enc (b,t,m)
__device__ float g_y1 [Bn * Tn * Mn];    // enc @ U_d^T
__device__ float g_S  [Bn * K2H];        // [d | sp] per batch row
__device__ float g_x1p[4 * Bn * Mn];     // x1 split-K partials (4 slices)
__device__ float g_G1p[2 * Bn * G4H];    // G1 split-K partials (2 slices)
__device__ float g_c  [Bn * Mn];
__device__ float g_gbias[G4H];           // b_ih + b_hh
__device__ float g_wv [513];             // folded W_y/v_y projection + const

__device__ __forceinline__ float tanh_mufu(float x) {      // attention only
    float y; asm("tanh.approx.f32 %0, %1;" : "=f"(y) : "f"(x)); return y;
}
__device__ __forceinline__ float tanh_acc(float x) {       // LSTM gates
    float e = __expf(2.f * x);
    return 1.f - __fdividef(2.f, e + 1.f);
}
__device__ __forceinline__ float sigm(float x) {
    return __fdividef(1.f, 1.f + __expf(-x));
}

// ---------------- prep: transpose enc, zero state, fold gate bias --------
__global__ void k_pre(const float* __restrict__ enc_in,
                      const float* __restrict__ b_ih,
                      const float* __restrict__ b_hh) {
    int idx = blockIdx.x * blockDim.x + threadIdx.x;
    int stride = gridDim.x * blockDim.x;
    for (int i = idx; i < Bn * Tn * Mn; i += stride) {
        int m = i & (Mn - 1);
        int t = (i >> 8) & (Tn - 1);
        int b = i >> 14;
        g_enc[i] = enc_in[(size_t)t * Bn * Mn + (size_t)b * Mn + m];
    }
    for (int i = idx; i < Bn * K2H; i += stride) g_S[i] = 0.f;
    for (int i = idx; i < G4H; i += stride) g_gbias[i] = b_ih[i] + b_hh[i];
}

// ---------------- fold final projection ----------------------------------
__global__ void k_wv(const float* __restrict__ W_y, const float* __restrict__ v_y,
                     const float* __restrict__ b_Wy, const float* __restrict__ b_vy) {
    int k = threadIdx.x;  // 512 threads
    float s = 0.f;
    for (int j = 0; j < Hn; j++) s += v_y[j] * W_y[(size_t)j * K2H + k];
    g_wv[k] = s;
    if (k == 0) {
        float s0 = 0.f;
        for (int j = 0; j < Hn; j++) s0 += v_y[j] * b_Wy[j];
        g_wv[512] = s0 + b_vy[0];
    }
}

// ---- GEMM core: C[m0..+64, n0..+64] = A[.,kb..kb+ksl] * W[.,kb..kb+ksl]^T
// 128 threads. Per-thread 8x4 register tile. Double-buffered SMEM staging
// (BK=16), one __syncthreads per stage, LDG for next stage overlaps compute.
__device__ __forceinline__ void gemm64x64(
    const float* __restrict__ A, int lda,
    const float* __restrict__ W, int ldw,
    float* __restrict__ C, int ldc,
    int m0, int n0, int kb, int ksl) {

    __shared__ __align__(16) float As[2][16 * 64];   // k-major: As[k][row]
    __shared__ __align__(16) float Ws[2][16 * 64];   // k-major: Ws[k][col]

    const int tid = threadIdx.x;
    const int tm = tid >> 4;              // 0..7  -> rows 8*tm
    const int tn = tid & 15;              // 0..15 -> cols 4*tn
    const int lr = tid >> 1;              // 0..63 loader row/col
    const int lc = (tid & 1) << 3;        // {0,8} loader k offset

    const float* Aptr = A + (size_t)(m0 + lr) * lda + kb + lc;
    const float* Wptr = W + (size_t)(n0 + lr) * ldw + kb + lc;

    float acc[8][4];
#pragma unroll
    for (int i = 0; i < 8; i++)
#pragma unroll
        for (int j = 0; j < 4; j++) acc[i][j] = 0.f;

    const int ns = ksl >> 4;              // # of BK=16 stages
    float4 ra0 = *(const float4*)(Aptr);
    float4 ra1 = *(const float4*)(Aptr + 4);
    float4 rw0 = *(const float4*)(Wptr);
    float4 rw1 = *(const float4*)(Wptr + 4);

    // deposit stage 0
    {
        float* a = As[0]; float* w = Ws[0];
        a[(lc + 0) * 64 + lr] = ra0.x; a[(lc + 1) * 64 + lr] = ra0.y;
        a[(lc + 2) * 64 + lr] = ra0.z; a[(lc + 3) * 64 + lr] = ra0.w;
        a[(lc + 4) * 64 + lr] = ra1.x; a[(lc + 5) * 64 + lr] = ra1.y;
        a[(lc + 6) * 64 + lr] = ra1.z; a[(lc + 7) * 64 + lr] = ra1.w;
        w[(lc + 0) * 64 + lr] = rw0.x; w[(lc + 1) * 64 + lr] = rw0.y;
        w[(lc + 2) * 64 + lr] = rw0.z; w[(lc + 3) * 64 + lr] = rw0.w;
        w[(lc + 4) * 64 + lr] = rw1.x; w[(lc + 5) * 64 + lr] = rw1.y;
        w[(lc + 6) * 64 + lr] = rw1.z; w[(lc + 7) * 64 + lr] = rw1.w;
    }
    __syncthreads();

    for (int s = 0; s < ns; s++) {
        const int cur = s & 1;
        if (s + 1 < ns) {                 // issue next stage's LDG early
            ra0 = *(const float4*)(Aptr + (s + 1) * 16);
            ra1 = *(const float4*)(Aptr + (s + 1) * 16 + 4);
            rw0 = *(const float4*)(Wptr + (s + 1) * 16);
            rw1 = *(const float4*)(Wptr + (s + 1) * 16 + 4);
        }
        const float* a = As[cur];
        const float* w = Ws[cur];
#pragma unroll
        for (int k = 0; k < 16; k++) {
            float4 a0 = *(const float4*)(a + k * 64 + 8 * tm);
            float4 a1 = *(const float4*)(a + k * 64 + 8 * tm + 4);
            float4 w0 = *(const float4*)(w + k * 64 + 4 * tn);
            acc[0][0] += a0.x * w0.x; acc[0][1] += a0.x * w0.y;
            acc[0][2] += a0.x * w0.z; acc[0][3] += a0.x * w0.w;
            acc[1][0] += a0.y * w0.x; acc[1][1] += a0.y * w0.y;
            acc[1][2] += a0.y * w0.z; acc[1][3] += a0.y * w0.w;
            acc[2][0] += a0.z * w0.x; acc[2][1] += a0.z * w0.y;
            acc[2][2] += a0.z * w0.z; acc[2][3] += a0.z * w0.w;
            acc[3][0] += a0.w * w0.x; acc[3][1] += a0.w * w0.y;
            acc[3][2] += a0.w * w0.z; acc[3][3] += a0.w * w0.w;
            acc[4][0] += a1.x * w0.x; acc[4][1] += a1.x * w0.y;
            acc[4][2] += a1.x * w0.z; acc[4][3] += a1.x * w0.w;
            acc[5][0] += a1.y * w0.x; acc[5][1] += a1.y * w0.y;
            acc[5][2] += a1.y * w0.z; acc[5][3] += a1.y * w0.w;
            acc[6][0] += a1.z * w0.x; acc[6][1] += a1.z * w0.y;
            acc[6][2] += a1.z * w0.z; acc[6][3] += a1.z * w0.w;
            acc[7][0] += a1.w * w0.x; acc[7][1] += a1.w * w0.y;
            acc[7][2] += a1.w * w0.z; acc[7][3] += a1.w * w0.w;
        }
        if (s + 1 < ns) {
            float* an = As[cur ^ 1]; float* wn = Ws[cur ^ 1];
            an[(lc + 0) * 64 + lr] = ra0.x; an[(lc + 1) * 64 + lr] = ra0.y;
            an[(lc + 2) * 64 + lr] = ra0.z; an[(lc + 3) * 64 + lr] = ra0.w;
            an[(lc + 4) * 64 + lr] = ra1.x; an[(lc + 5) * 64 + lr] = ra1.y;
            an[(lc + 6) * 64 + lr] = ra1.z; an[(lc + 7) * 64 + lr] = ra1.w;
            wn[(lc + 0) * 64 + lr] = rw0.x; wn[(lc + 1) * 64 + lr] = rw0.y;
            wn[(lc + 2) * 64 + lr] = rw0.z; wn[(lc + 3) * 64 + lr] = rw0.w;
            wn[(lc + 4) * 64 + lr] = rw1.x; wn[(lc + 5) * 64 + lr] = rw1.y;
            wn[(lc + 6) * 64 + lr] = rw1.z; wn[(lc + 7) * 64 + lr] = rw1.w;
            __syncthreads();
        }
    }

#pragma unroll
    for (int i = 0; i < 8; i++) {
        float4 cv; cv.x = acc[i][0]; cv.y = acc[i][1];
        cv.z = acc[i][2]; cv.w = acc[i][3];
        *(float4*)(C + (size_t)(m0 + 8 * tm + i) * ldc + n0 + 4 * tn) = cv;
    }
}

// ---------------- per-step fused GEMM with block-level split-K ------------
// blocks 0..63  : x1 partials  (256x256, K=512 -> 4 slices of 128)
// blocks 64..191: G1 partials  (256x1024, K=256 -> 2 slices of 128)
__global__ void __launch_bounds__(128) k_stepgemm(
        const float* __restrict__ W_d, const float* __restrict__ W_hh) {
    const int id = blockIdx.x;
    if (id < 64) {
        int s  = id & 3;
        int n0 = ((id >> 2) & 3) * 64;
        int m0 = (id >> 4) * 64;
        gemm64x64(g_S, K2H, W_d, K2H, g_x1p + s * (Bn * Mn), Mn,
                  m0, n0, s * 128, 128);
    } else {
        int j  = id - 64;
        int s  = j & 1;
        int n0 = ((j >> 1) & 15) * 64;
        int m0 = (j >> 5) * 64;
        gemm64x64(g_S, K2H, W_hh, Hn, g_G1p + s * (Bn * G4H), G4H,
                  m0, n0, s * 128, 128);
    }
}

// ---------------- one-time y1 GEMM -----------------------------------------
__global__ void __launch_bounds__(128) k_y1(const float* __restrict__ U_d) {
    int id = blockIdx.x;                 // 1024 blocks
    int m0 = (id >> 2) * 64;
    int n0 = (id & 3) * 64;
    gemm64x64(g_enc, Mn, U_d, Mn, g_y1, Mn, m0, n0, 0, Mn);
}

// ---------------- per-batch attention + LSTM cell update ------------------
__global__ void __launch_bounds__(256) k_attn(
        const float* __restrict__ y_in, const float* __restrict__ v_d,
        const float* __restrict__ w_til, const float* __restrict__ b_wt,
        const float* __restrict__ W_ih, const float* __restrict__ b_Wd,
        int t_step) {
    int b = blockIdx.x, tid = threadIdx.x;
    int warp = tid >> 5, lane = tid & 31;
    __shared__ float sx[Mn], sv[Mn], sl[Tn], sred[8];
    __shared__ float s_ytil;

    // x1 = sum of 4 split-K partials + bias
    {
        int o = b * Mn + tid;
        sx[tid] = g_x1p[o] + g_x1p[Bn * Mn + o] + g_x1p[2 * Bn * Mn + o]
                + g_x1p[3 * Bn * Mn + o] + b_Wd[tid];
    }
    sv[tid] = v_d[tid];
    __syncthreads();

    const float* y1b = g_y1 + (size_t)b * Tn * Mn;
#pragma unroll
    for (int i = 0; i < 8; i++) {
        int t = warp * 8 + i;
        const float* row = y1b + t * Mn;
        float acc = 0.f;
#pragma unroll
        for (int j = 0; j < 8; j++) {
            int m = lane + 32 * j;
            acc += tanh_mufu(sx[m] + row[m]) * sv[m];
        }
#pragma unroll
        for (int o = 16; o > 0; o >>= 1) acc += __shfl_xor_sync(0xffffffffu, acc, o);
        if (lane == 0) sl[t] = acc;
    }
    __syncthreads();

    if (warp == 0) {
        float v0 = sl[lane], v1 = sl[lane + 32];
        float mx = fmaxf(v0, v1);
#pragma unroll
        for (int o = 16; o > 0; o >>= 1) mx = fmaxf(mx, __shfl_xor_sync(0xffffffffu, mx, o));
        float e0 = __expf(v0 - mx), e1 = __expf(v1 - mx);
        float s = e0 + e1;
#pragma unroll
        for (int o = 16; o > 0; o >>= 1) s += __shfl_xor_sync(0xffffffffu, s, o);
        float inv = __fdividef(1.f, s);
        sl[lane] = e0 * inv; sl[lane + 32] = e1 * inv;
    }
    __syncthreads();

    const float* encb = g_enc + (size_t)b * Tn * Mn;
    float c = 0.f;
#pragma unroll 8
    for (int t = 0; t < Tn; t++) c += sl[t] * encb[t * Mn + tid];
    g_c[b * Mn + tid] = c;

    float part = c * w_til[tid];
#pragma unroll
    for (int o = 16; o > 0; o >>= 1) part += __shfl_xor_sync(0xffffffffu, part, o);
    if (lane == 0) sred[warp] = part;
    __syncthreads();
    if (tid == 0) {
        float s = 0.f;
#pragma unroll
        for (int w = 0; w < 8; w++) s += sred[w];
        s_ytil = s + w_til[Mn] * y_in[b * Tn + t_step] + b_wt[0];
    }
    __syncthreads();
    float yt = s_ytil;

    // gates = yt*W_ih + (G1 partial0 + partial1 + gbias)
    const float* G0 = g_G1p + b * G4H;
    const float* G1 = g_G1p + Bn * G4H + b * G4H;
    float ig = yt * W_ih[tid]          + G0[tid]          + G1[tid]          + g_gbias[tid];
    float fg = yt * W_ih[Hn + tid]     + G0[Hn + tid]     + G1[Hn + tid]     + g_gbias[Hn + tid];
    float gg = yt * W_ih[2 * Hn + tid] + G0[2 * Hn + tid] + G1[2 * Hn + tid] + g_gbias[2 * Hn + tid];
    float og = yt * W_ih[3 * Hn + tid] + G0[3 * Hn + tid] + G1[3 * Hn + tid] + g_gbias[3 * Hn + tid];
    float sp = g_S[b * K2H + Hn + tid];
    float spn = sigm(fg) * sp + sigm(ig) * tanh_acc(gg);
    float dn  = sigm(og) * tanh_acc(spn);
    g_S[b * K2H + tid]      = dn;
    g_S[b * K2H + Hn + tid] = spn;
}

// ---------------- folded output: out[b] = [d|c] . wv + const --------------
__global__ void k_out(float* __restrict__ out) {
    int b = blockIdx.x, tid = threadIdx.x;
    int warp = tid >> 5, lane = tid & 31;
    __shared__ float sred[8];
    float p = g_S[b * K2H + tid] * g_wv[tid] + g_c[b * Mn + tid] * g_wv[Hn + tid];
#pragma unroll
    for (int o = 16; o > 0; o >>= 1) p += __shfl_xor_sync(0xffffffffu, p, o);
    if (lane == 0) sred[warp] = p;
    __syncthreads();
    if (tid == 0) {
        float s = 0.f;
#pragma unroll
        for (int w = 0; w < 8; w++) s += sred[w];
        out[b] = s + g_wv[512];
    }
}

extern "C" void kernel_launch(void* const* d_in, const int* in_sizes, int n_in,
                              void* d_out, int out_size) {
    const float* enc  = (const float*)d_in[0];
    const float* y    = (const float*)d_in[1];
    const float* W_d  = (const float*)d_in[2];
    const float* b_Wd = (const float*)d_in[3];
    const float* U_d  = (const float*)d_in[4];
    const float* v_d  = (const float*)d_in[5];
    const float* w_t  = (const float*)d_in[6];
    const float* b_wt = (const float*)d_in[7];
    const float* W_ih = (const float*)d_in[8];
    const float* W_hh = (const float*)d_in[9];
    const float* b_ih = (const float*)d_in[10];
    const float* b_hh = (const float*)d_in[11];
    const float* W_y  = (const float*)d_in[12];
    const float* b_Wy = (const float*)d_in[13];
    const float* v_y  = (const float*)d_in[14];
    const float* b_vy = (const float*)d_in[15];

    k_pre<<<2048, 256>>>(enc, b_ih, b_hh);
    k_wv<<<1, 512>>>(W_y, v_y, b_Wy, b_vy);
    k_y1<<<1024, 128>>>(U_d);
    for (int t = 0; t < Tn; t++) {
        k_stepgemm<<<192, 128>>>(W_d, W_hh);
        k_attn<<<256, 256>>>(y, v_d, w_t, b_wt, W_ih, b_Wd, t);
    }
    k_out<<<256, 256>>>((float*)d_out);
}

// round 5
// speedup vs baseline: 2.1397x; 1.1557x over previous
#include <cuda_runtime.h>

namespace {
constexpr int Bn = 256, Tn = 64, Mn = 256, Hn = 256, K2H = 512, G4H = 1024;
constexpr int NSX = 8;   // split-K slices for x1 (K=512 -> ksl 64)
constexpr int NSG = 4;   // split-K slices for G1 (K=256 -> ksl 64)
}

// ---------------- device scratch (no allocations allowed) ----------------
__device__ float g_enc[Bn * Tn * Mn];       // enc (b,t,m)
__device__ float g_y1 [Bn * Tn * Mn];       // enc @ U_d^T
__device__ float g_S  [Bn * K2H];           // [d | sp] per batch row
__device__ float g_x1p[NSX * Bn * Mn];      // x1 split-K partials
__device__ float g_G1p[NSG * Bn * G4H];     // G1 split-K partials
__device__ float g_c  [Bn * Mn];
__device__ float g_gbias[G4H];              // b_ih + b_hh
__device__ float g_wv [513];                // folded W_y/v_y projection + const

__device__ __forceinline__ float tanh_mufu(float x) {      // attention only
    float y; asm("tanh.approx.f32 %0, %1;" : "=f"(y) : "f"(x)); return y;
}
__device__ __forceinline__ float tanh_acc(float x) {       // LSTM gates
    float e = __expf(2.f * x);
    return 1.f - __fdividef(2.f, e + 1.f);
}
__device__ __forceinline__ float sigm(float x) {
    return __fdividef(1.f, 1.f + __expf(-x));
}

// ---------------- prep: transpose enc, zero state, fold gate bias --------
__global__ void k_pre(const float* __restrict__ enc_in,
                      const float* __restrict__ b_ih,
                      const float* __restrict__ b_hh) {
    int idx = blockIdx.x * blockDim.x + threadIdx.x;
    int stride = gridDim.x * blockDim.x;
    for (int i = idx; i < Bn * Tn * Mn; i += stride) {
        int m = i & (Mn - 1);
        int t = (i >> 8) & (Tn - 1);
        int b = i >> 14;
        g_enc[i] = enc_in[(size_t)t * Bn * Mn + (size_t)b * Mn + m];
    }
    for (int i = idx; i < Bn * K2H; i += stride) g_S[i] = 0.f;
    for (int i = idx; i < G4H; i += stride) g_gbias[i] = b_ih[i] + b_hh[i];
}

// ---------------- fold final projection ----------------------------------
__global__ void k_wv(const float* __restrict__ W_y, const float* __restrict__ v_y,
                     const float* __restrict__ b_Wy, const float* __restrict__ b_vy) {
    int k = threadIdx.x;  // 512 threads
    float s = 0.f;
    for (int j = 0; j < Hn; j++) s += v_y[j] * W_y[(size_t)j * K2H + k];
    g_wv[k] = s;
    if (k == 0) {
        float s0 = 0.f;
        for (int j = 0; j < Hn; j++) s0 += v_y[j] * b_Wy[j];
        g_wv[512] = s0 + b_vy[0];
    }
}

// ---- GEMM core: C[m0..+64, n0..+64] = A[.,kb..kb+ksl] * W[.,kb..kb+ksl]^T
// 128 threads, 8x4 per-thread register tile, double-buffered SMEM (BK=16).
__device__ __forceinline__ void gemm64x64(
    const float* __restrict__ A, int lda,
    const float* __restrict__ W, int ldw,
    float* __restrict__ C, int ldc,
    int m0, int n0, int kb, int ksl) {

    __shared__ __align__(16) float As[2][16 * 64];   // k-major: As[k][row]
    __shared__ __align__(16) float Ws[2][16 * 64];   // k-major: Ws[k][col]

    const int tid = threadIdx.x;
    const int tm = tid >> 4;              // 0..7  -> rows 8*tm
    const int tn = tid & 15;              // 0..15 -> cols 4*tn
    const int lr = tid >> 1;              // 0..63 loader row/col
    const int lc = (tid & 1) << 3;        // {0,8} loader k offset

    const float* Aptr = A + (size_t)(m0 + lr) * lda + kb + lc;
    const float* Wptr = W + (size_t)(n0 + lr) * ldw + kb + lc;

    float acc[8][4];
#pragma unroll
    for (int i = 0; i < 8; i++)
#pragma unroll
        for (int j = 0; j < 4; j++) acc[i][j] = 0.f;

    const int ns = ksl >> 4;              // # of BK=16 stages
    float4 ra0 = *(const float4*)(Aptr);
    float4 ra1 = *(const float4*)(Aptr + 4);
    float4 rw0 = *(const float4*)(Wptr);
    float4 rw1 = *(const float4*)(Wptr + 4);

    {   // deposit stage 0
        float* a = As[0]; float* w = Ws[0];
        a[(lc + 0) * 64 + lr] = ra0.x; a[(lc + 1) * 64 + lr] = ra0.y;
        a[(lc + 2) * 64 + lr] = ra0.z; a[(lc + 3) * 64 + lr] = ra0.w;
        a[(lc + 4) * 64 + lr] = ra1.x; a[(lc + 5) * 64 + lr] = ra1.y;
        a[(lc + 6) * 64 + lr] = ra1.z; a[(lc + 7) * 64 + lr] = ra1.w;
        w[(lc + 0) * 64 + lr] = rw0.x; w[(lc + 1) * 64 + lr] = rw0.y;
        w[(lc + 2) * 64 + lr] = rw0.z; w[(lc + 3) * 64 + lr] = rw0.w;
        w[(lc + 4) * 64 + lr] = rw1.x; w[(lc + 5) * 64 + lr] = rw1.y;
        w[(lc + 6) * 64 + lr] = rw1.z; w[(lc + 7) * 64 + lr] = rw1.w;
    }
    __syncthreads();

    for (int s = 0; s < ns; s++) {
        const int cur = s & 1;
        if (s + 1 < ns) {                 // issue next stage's LDG early
            ra0 = *(const float4*)(Aptr + (s + 1) * 16);
            ra1 = *(const float4*)(Aptr + (s + 1) * 16 + 4);
            rw0 = *(const float4*)(Wptr + (s + 1) * 16);
            rw1 = *(const float4*)(Wptr + (s + 1) * 16 + 4);
        }
        const float* a = As[cur];
        const float* w = Ws[cur];
#pragma unroll
        for (int k = 0; k < 16; k++) {
            float4 a0 = *(const float4*)(a + k * 64 + 8 * tm);
            float4 a1 = *(const float4*)(a + k * 64 + 8 * tm + 4);
            float4 w0 = *(const float4*)(w + k * 64 + 4 * tn);
            acc[0][0] += a0.x * w0.x; acc[0][1] += a0.x * w0.y;
            acc[0][2] += a0.x * w0.z; acc[0][3] += a0.x * w0.w;
            acc[1][0] += a0.y * w0.x; acc[1][1] += a0.y * w0.y;
            acc[1][2] += a0.y * w0.z; acc[1][3] += a0.y * w0.w;
            acc[2][0] += a0.z * w0.x; acc[2][1] += a0.z * w0.y;
            acc[2][2] += a0.z * w0.z; acc[2][3] += a0.z * w0.w;
            acc[3][0] += a0.w * w0.x; acc[3][1] += a0.w * w0.y;
            acc[3][2] += a0.w * w0.z; acc[3][3] += a0.w * w0.w;
            acc[4][0] += a1.x * w0.x; acc[4][1] += a1.x * w0.y;
            acc[4][2] += a1.x * w0.z; acc[4][3] += a1.x * w0.w;
            acc[5][0] += a1.y * w0.x; acc[5][1] += a1.y * w0.y;
            acc[5][2] += a1.y * w0.z; acc[5][3] += a1.y * w0.w;
            acc[6][0] += a1.z * w0.x; acc[6][1] += a1.z * w0.y;
            acc[6][2] += a1.z * w0.z; acc[6][3] += a1.z * w0.w;
            acc[7][0] += a1.w * w0.x; acc[7][1] += a1.w * w0.y;
            acc[7][2] += a1.w * w0.z; acc[7][3] += a1.w * w0.w;
        }
        if (s + 1 < ns) {
            float* an = As[cur ^ 1]; float* wn = Ws[cur ^ 1];
            an[(lc + 0) * 64 + lr] = ra0.x; an[(lc + 1) * 64 + lr] = ra0.y;
            an[(lc + 2) * 64 + lr] = ra0.z; an[(lc + 3) * 64 + lr] = ra0.w;
            an[(lc + 4) * 64 + lr] = ra1.x; an[(lc + 5) * 64 + lr] = ra1.y;
            an[(lc + 6) * 64 + lr] = ra1.z; an[(lc + 7) * 64 + lr] = ra1.w;
            wn[(lc + 0) * 64 + lr] = rw0.x; wn[(lc + 1) * 64 + lr] = rw0.y;
            wn[(lc + 2) * 64 + lr] = rw0.z; wn[(lc + 3) * 64 + lr] = rw0.w;
            wn[(lc + 4) * 64 + lr] = rw1.x; wn[(lc + 5) * 64 + lr] = rw1.y;
            wn[(lc + 6) * 64 + lr] = rw1.z; wn[(lc + 7) * 64 + lr] = rw1.w;
            __syncthreads();
        }
    }

#pragma unroll
    for (int i = 0; i < 8; i++) {
        float4 cv; cv.x = acc[i][0]; cv.y = acc[i][1];
        cv.z = acc[i][2]; cv.w = acc[i][3];
        *(float4*)(C + (size_t)(m0 + 8 * tm + i) * ldc + n0 + 4 * tn) = cv;
    }
}

// ---------------- per-step fused GEMM, uniform 64x64x64 jobs --------------
// blocks 0..127  : x1 partials  (4m x 4n x 8 K-slices)
// blocks 128..383: G1 partials  (4m x 16n x 4 K-slices)
__global__ void __launch_bounds__(128) k_stepgemm(
        const float* __restrict__ W_d, const float* __restrict__ W_hh) {
    const int id = blockIdx.x;
    if (id < 128) {
        int s  = id & 7;
        int n0 = ((id >> 3) & 3) * 64;
        int m0 = (id >> 5) * 64;
        gemm64x64(g_S, K2H, W_d, K2H, g_x1p + s * (Bn * Mn), Mn,
                  m0, n0, s * 64, 64);
    } else {
        int j  = id - 128;
        int s  = j & 3;
        int n0 = ((j >> 2) & 15) * 64;
        int m0 = (j >> 6) * 64;
        gemm64x64(g_S, K2H, W_hh, Hn, g_G1p + s * (Bn * G4H), G4H,
                  m0, n0, s * 64, 64);
    }
}

// ---------------- one-time y1 GEMM -----------------------------------------
__global__ void __launch_bounds__(128) k_y1(const float* __restrict__ U_d) {
    int id = blockIdx.x;                 // 1024 blocks
    int m0 = (id >> 2) * 64;
    int n0 = (id & 3) * 64;
    gemm64x64(g_enc, Mn, U_d, Mn, g_y1, Mn, m0, n0, 0, Mn);
}

// ---------------- per-batch attention + LSTM cell update ------------------
__global__ void __launch_bounds__(256) k_attn(
        const float* __restrict__ y_in, const float* __restrict__ v_d,
        const float* __restrict__ w_til, const float* __restrict__ b_wt,
        const float* __restrict__ W_ih, const float* __restrict__ b_Wd,
        int t_step) {
    int b = blockIdx.x, tid = threadIdx.x;
    int warp = tid >> 5, lane = tid & 31;
    __shared__ float sx[Mn], sv[Mn], sl[Tn], sred[8];
    __shared__ float s_ytil;

    // x1 = sum of NSX split-K partials + bias
    {
        int o = b * Mn + tid;
        float v = b_Wd[tid];
#pragma unroll
        for (int s = 0; s < NSX; s++) v += g_x1p[s * (Bn * Mn) + o];
        sx[tid] = v;
    }
    sv[tid] = v_d[tid];
    __syncthreads();

    const float* y1b = g_y1 + (size_t)b * Tn * Mn;
#pragma unroll
    for (int i = 0; i < 8; i++) {
        int t = warp * 8 + i;
        const float* row = y1b + t * Mn;
        float acc = 0.f;
#pragma unroll
        for (int j = 0; j < 8; j++) {
            int m = lane + 32 * j;
            acc += tanh_mufu(sx[m] + row[m]) * sv[m];
        }
#pragma unroll
        for (int o = 16; o > 0; o >>= 1) acc += __shfl_xor_sync(0xffffffffu, acc, o);
        if (lane == 0) sl[t] = acc;
    }
    __syncthreads();

    if (warp == 0) {
        float v0 = sl[lane], v1 = sl[lane + 32];
        float mx = fmaxf(v0, v1);
#pragma unroll
        for (int o = 16; o > 0; o >>= 1) mx = fmaxf(mx, __shfl_xor_sync(0xffffffffu, mx, o));
        float e0 = __expf(v0 - mx), e1 = __expf(v1 - mx);
        float s = e0 + e1;
#pragma unroll
        for (int o = 16; o > 0; o >>= 1) s += __shfl_xor_sync(0xffffffffu, s, o);
        float inv = __fdividef(1.f, s);
        sl[lane] = e0 * inv; sl[lane + 32] = e1 * inv;
    }
    __syncthreads();

    const float* encb = g_enc + (size_t)b * Tn * Mn;
    float c = 0.f;
#pragma unroll 8
    for (int t = 0; t < Tn; t++) c += sl[t] * encb[t * Mn + tid];
    g_c[b * Mn + tid] = c;

    float part = c * w_til[tid];
#pragma unroll
    for (int o = 16; o > 0; o >>= 1) part += __shfl_xor_sync(0xffffffffu, part, o);
    if (lane == 0) sred[warp] = part;
    __syncthreads();
    if (tid == 0) {
        float s = 0.f;
#pragma unroll
        for (int w = 0; w < 8; w++) s += sred[w];
        s_ytil = s + w_til[Mn] * y_in[b * Tn + t_step] + b_wt[0];
    }
    __syncthreads();
    float yt = s_ytil;

    // gates[q] = yt*W_ih + sum(G1 partials) + gbias
    float gate[4];
#pragma unroll
    for (int q = 0; q < 4; q++) {
        int idx = q * Hn + tid;
        float v = g_gbias[idx] + yt * W_ih[idx];
#pragma unroll
        for (int s = 0; s < NSG; s++)
            v += g_G1p[s * (Bn * G4H) + b * G4H + idx];
        gate[q] = v;
    }
    float sp = g_S[b * K2H + Hn + tid];
    float spn = sigm(gate[1]) * sp + sigm(gate[0]) * tanh_acc(gate[2]);
    float dn  = sigm(gate[3]) * tanh_acc(spn);
    g_S[b * K2H + tid]      = dn;
    g_S[b * K2H + Hn + tid] = spn;
}

// ---------------- folded output: out[b] = [d|c] . wv + const --------------
__global__ void k_out(float* __restrict__ out) {
    int b = blockIdx.x, tid = threadIdx.x;
    int warp = tid >> 5, lane = tid & 31;
    __shared__ float sred[8];
    float p = g_S[b * K2H + tid] * g_wv[tid] + g_c[b * Mn + tid] * g_wv[Hn + tid];
#pragma unroll
    for (int o = 16; o > 0; o >>= 1) p += __shfl_xor_sync(0xffffffffu, p, o);
    if (lane == 0) sred[warp] = p;
    __syncthreads();
    if (tid == 0) {
        float s = 0.f;
#pragma unroll
        for (int w = 0; w < 8; w++) s += sred[w];
        out[b] = s + g_wv[512];
    }
}

extern "C" void kernel_launch(void* const* d_in, const int* in_sizes, int n_in,
                              void* d_out, int out_size) {
    const float* enc  = (const float*)d_in[0];
    const float* y    = (const float*)d_in[1];
    const float* W_d  = (const float*)d_in[2];
    const float* b_Wd = (const float*)d_in[3];
    const float* U_d  = (const float*)d_in[4];
    const float* v_d  = (const float*)d_in[5];
    const float* w_t  = (const float*)d_in[6];
    const float* b_wt = (const float*)d_in[7];
    const float* W_ih = (const float*)d_in[8];
    const float* W_hh = (const float*)d_in[9];
    const float* b_ih = (const float*)d_in[10];
    const float* b_hh = (const float*)d_in[11];
    const float* W_y  = (const float*)d_in[12];
    const float* b_Wy = (const float*)d_in[13];
    const float* v_y  = (const float*)d_in[14];
    const float* b_vy = (const float*)d_in[15];

    k_pre<<<2048, 256>>>(enc, b_ih, b_hh);
    k_wv<<<1, 512>>>(W_y, v_y, b_Wy, b_vy);
    k_y1<<<1024, 128>>>(U_d);
    for (int t = 0; t < Tn; t++) {
        k_stepgemm<<<384, 128>>>(W_d, W_hh);
        k_attn<<<256, 256>>>(y, v_d, w_t, b_wt, W_ih, b_Wd, t);
    }
    k_out<<<256, 256>>>((float*)d_out);
}